// round 7
// baseline (speedup 1.0000x reference)
#include <cuda_runtime.h>
#include <math.h>
#include <stdint.h>

// Problem constants
#define B 16
#define S 2048
#define M 4
#define E 128
#define HH 128
#define VOCAB 100000
#define NE 4000
#define NR 200
#define FULLMASK 0xffffffffu

// ---------------- device scratch (no allocation allowed) ----------------
__device__ float g_h[B * HH];
__device__ float g_u[B * HH];
__device__ float g_logit[B * S];
__device__ int   g_cnt[2 * B];   // per-batch arrival counters, hop 0/1

// ---------------- threefry2x32-20 (JAX) ----------------
__host__ __device__ __forceinline__ uint32_t rotl32(uint32_t v, int d) {
    return (v << d) | (v >> (32 - d));
}

__host__ __device__ __forceinline__ void threefry2x32(
    uint32_t k0, uint32_t k1, uint32_t x0, uint32_t x1,
    uint32_t& o0, uint32_t& o1)
{
    uint32_t ks0 = k0, ks1 = k1;
    uint32_t ks2 = k0 ^ k1 ^ 0x1BD11BDAu;
    x0 += ks0; x1 += ks1;
    const int rA[4] = {13, 15, 26, 6};
    const int rB[4] = {17, 29, 16, 24};
    #pragma unroll
    for (int i = 0; i < 4; i++) { x0 += x1; x1 = rotl32(x1, rA[i]); x1 ^= x0; }
    x0 += ks1; x1 += ks2 + 1u;
    #pragma unroll
    for (int i = 0; i < 4; i++) { x0 += x1; x1 = rotl32(x1, rB[i]); x1 ^= x0; }
    x0 += ks2; x1 += ks0 + 2u;
    #pragma unroll
    for (int i = 0; i < 4; i++) { x0 += x1; x1 = rotl32(x1, rA[i]); x1 ^= x0; }
    x0 += ks0; x1 += ks1 + 3u;
    #pragma unroll
    for (int i = 0; i < 4; i++) { x0 += x1; x1 = rotl32(x1, rB[i]); x1 ^= x0; }
    x0 += ks1; x1 += ks2 + 4u;
    #pragma unroll
    for (int i = 0; i < 4; i++) { x0 += x1; x1 = rotl32(x1, rA[i]); x1 ^= x0; }
    x0 += ks2; x1 += ks0 + 5u;
    o0 = x0; o1 = x1;
}

// ---------------- h = hidden @ Wm^T + Wb ; u = h ; reset barrier counters ----
__global__ void k_h(const float* __restrict__ hidden,
                    const float* __restrict__ Wm,
                    const float* __restrict__ Wb)
{
    int b = blockIdx.x, t = threadIdx.x;
    if (t == 0) { g_cnt[b] = 0; g_cnt[B + b] = 0; }
    __shared__ float sh[HH];
    sh[t] = hidden[b * HH + t];
    __syncthreads();
    float acc = Wb[t];
    const float* w = Wm + (size_t)t * HH;
    #pragma unroll 8
    for (int k = 0; k < HH; k++) acc = fmaf(w[k], sh[k], acc);
    g_h[b * HH + t] = acc;
    g_u[b * HH + t] = acc;
}

// ============ K1: fused hop-0 logit gather  +  three head GEMVs ============
#define LB (B * S / 2 * 32 / 256)        // 2048
#define HEADW (2 + NE + NR)              // 4202 warps
#define HB ((HEADW * 32 + 255) / 256)    // 526

__global__ void k_fused1(const int* __restrict__ story,
                         const float* __restrict__ C0,
                         const float* __restrict__ W1w, const float* __restrict__ W1b,
                         const float* __restrict__ W3w, const float* __restrict__ W3b,
                         const float* __restrict__ W4w, const float* __restrict__ W4b,
                         float* __restrict__ o_sp, float* __restrict__ o_qh,
                         float* __restrict__ o_qt)
{
    if (blockIdx.x < LB) {
        int gid  = blockIdx.x * blockDim.x + threadIdx.x;
        int warp = gid >> 5, lane = gid & 31;
        int s0 = warp * 2;
        int b  = s0 >> 11;
        int4 ia = __ldg((const int4*)story + s0);
        int4 ib = __ldg((const int4*)story + s0 + 1);
        float4 a0 = __ldg((const float4*)(C0 + (size_t)ia.x * E) + lane);
        float4 a1 = __ldg((const float4*)(C0 + (size_t)ia.y * E) + lane);
        float4 a2 = __ldg((const float4*)(C0 + (size_t)ia.z * E) + lane);
        float4 a3 = __ldg((const float4*)(C0 + (size_t)ia.w * E) + lane);
        float4 b0 = __ldg((const float4*)(C0 + (size_t)ib.x * E) + lane);
        float4 b1 = __ldg((const float4*)(C0 + (size_t)ib.y * E) + lane);
        float4 b2 = __ldg((const float4*)(C0 + (size_t)ib.z * E) + lane);
        float4 b3 = __ldg((const float4*)(C0 + (size_t)ib.w * E) + lane);
        float4 u4 = *((const float4*)(g_u + b * HH) + lane);
        float sa = (a0.x + a1.x + a2.x + a3.x) * u4.x
                 + (a0.y + a1.y + a2.y + a3.y) * u4.y
                 + (a0.z + a1.z + a2.z + a3.z) * u4.z
                 + (a0.w + a1.w + a2.w + a3.w) * u4.w;
        float sb = (b0.x + b1.x + b2.x + b3.x) * u4.x
                 + (b0.y + b1.y + b2.y + b3.y) * u4.y
                 + (b0.z + b1.z + b2.z + b3.z) * u4.z
                 + (b0.w + b1.w + b2.w + b3.w) * u4.w;
        #pragma unroll
        for (int o = 16; o; o >>= 1) {
            sa += __shfl_down_sync(FULLMASK, sa, o);
            sb += __shfl_down_sync(FULLMASK, sb, o);
        }
        if (lane == 0) { g_logit[s0] = sa; g_logit[s0 + 1] = sb; }
    } else {
        int gid  = (blockIdx.x - LB) * blockDim.x + threadIdx.x;
        int w    = gid >> 5, lane = gid & 31;
        if (w >= HEADW) return;
        const float *W, *bias; float* outl; int N, n;
        if (w < 2)            { W = W1w; bias = W1b; outl = o_sp; N = 2;  n = w; }
        else if (w < 2 + NE)  { W = W3w; bias = W3b; outl = o_qh; N = NE; n = w - 2; }
        else                  { W = W4w; bias = W4b; outl = o_qt; N = NR; n = w - 2 - NE; }

        float4 w4 = __ldg((const float4*)(W + (size_t)n * HH) + lane);
        float  bs = __ldg(bias + n);
        #pragma unroll
        for (int b = 0; b < B; b++) {
            float4 h4 = *((const float4*)(g_h + b * HH) + lane);
            float s = w4.x * h4.x + w4.y * h4.y + w4.z * h4.z + w4.w * h4.w;
            #pragma unroll
            for (int o = 16; o; o >>= 1) s += __shfl_down_sync(FULLMASK, s, o);
            if (lane == 0) outl[b * N + n] = s + bs;
        }
    }
}

// ---------------- gumbel argmax one-hot body (for piggyback blocks) ----------------
__device__ __forceinline__ void argmax_body(const float* __restrict__ o_sp,
                                            const float* __restrict__ o_qh,
                                            const float* __restrict__ o_qt,
                                            float* __restrict__ a_sp,
                                            float* __restrict__ a_qh,
                                            float* __restrict__ a_qt,
                                            uint32_t k1a, uint32_t k1b,
                                            uint32_t k2a, uint32_t k2b,
                                            uint32_t k3a, uint32_t k3b,
                                            int blk2)
{
    int head = blk2 >> 4, b = blk2 & 15, t = threadIdx.x;
    const float* L; float* A; int N; uint32_t ka, kb;
    if (head == 0)      { L = o_sp; A = a_sp; N = 2;  ka = k1a; kb = k1b; }
    else if (head == 1) { L = o_qh; A = a_qh; N = NE; ka = k2a; kb = k2b; }
    else                { L = o_qt; A = a_qt; N = NR; ka = k3a; kb = k3b; }

    float bv = -INFINITY; int bi = 0x7fffffff;
    for (int i = t; i < N; i += 256) {
        int idx = b * N + i;
        float logit = __ldg(L + idx);
        uint32_t o0, o1;
        threefry2x32(ka, kb, 0u, (uint32_t)idx, o0, o1);
        uint32_t bits = o0 ^ o1;
        float u = __uint_as_float((bits >> 9) | 0x3F800000u) - 1.0f;
        float v = fmaxf(1e-10f, u + 1e-10f);
        float g = -logf(-logf(v));
        float nv = logit + g;
        if (nv > bv || (nv == bv && i < bi)) { bv = nv; bi = i; }
    }
    __shared__ float sv[256];
    __shared__ int   si[256];
    sv[t] = bv; si[t] = bi;
    __syncthreads();
    for (int o = 128; o; o >>= 1) {
        if (t < o) {
            if (sv[t + o] > sv[t] || (sv[t + o] == sv[t] && si[t + o] < si[t])) {
                sv[t] = sv[t + o]; si[t] = si[t + o];
            }
        }
        __syncthreads();
    }
    int best = si[0];
    float* out = A + b * N;
    for (int i = t; i < N; i += 256) out[i] = (i == best) ? 1.0f : 0.0f;
}

// ============ hop step: softmax + gather + u update + batch barrier + logits ======
// blocks [0,256): 16 per batch, 128 slots each; warp w owns 16 slots.
// Gathered slot embeddings parked in 64KB dynamic smem; after a per-batch arrival
// barrier (16 blocks, all co-resident), next-hop logits are computed from smem
// against the freshly-updated u (read with __ldcg, bypassing L1).
// FINAL=false also carries 48 argmax blocks [256,304).
template<bool FINAL>
__global__ void k_hop_step(const int* __restrict__ story,
                           const float* __restrict__ Ct,
                           int cidx,
                           const int* __restrict__ lengths,
                           float* __restrict__ out_mask,
                           const float* __restrict__ o_sp, const float* __restrict__ o_qh,
                           const float* __restrict__ o_qt,
                           float* __restrict__ a_sp, float* __restrict__ a_qh,
                           float* __restrict__ a_qt,
                           uint32_t k1a, uint32_t k1b, uint32_t k2a, uint32_t k2b,
                           uint32_t k3a, uint32_t k3b)
{
    extern __shared__ float s_emb[];   // 128 slots x 128 floats = 64KB

    if (!FINAL && blockIdx.x >= 256) {
        argmax_body(o_sp, o_qh, o_qt, a_sp, a_qh, a_qt,
                    k1a, k1b, k2a, k2b, k3a, k3b, blockIdx.x - 256);
        return;
    }

    int blk = blockIdx.x;
    int b   = blk >> 4;
    int slot0 = (blk & 15) * 128;
    int t = threadIdx.x, lane = t & 31, w = t >> 5;

    // ---- phase A: softmax stats over this batch's logits ----
    const float* l = g_logit + b * S;
    __shared__ float red[256];
    float m = -INFINITY;
    for (int i = t; i < S; i += 256) m = fmaxf(m, __ldg(l + i));
    red[t] = m; __syncthreads();
    #pragma unroll
    for (int o = 128; o; o >>= 1) { if (t < o) red[t] = fmaxf(red[t], red[t + o]); __syncthreads(); }
    m = red[0]; __syncthreads();
    float sum = 0.f;
    for (int i = t; i < S; i += 256) sum += expf(__ldg(l + i) - m);
    red[t] = sum; __syncthreads();
    #pragma unroll
    for (int o = 128; o; o >>= 1) { if (t < o) red[t] += red[t + o]; __syncthreads(); }
    float inv = 1.0f / red[0];
    __syncthreads();

    // ---- phase B: gather + weighted accumulate + park emb in smem ----
    float4 acc = make_float4(0.f, 0.f, 0.f, 0.f);
    int sbase = b * S + slot0 + w * 16;   // global slot base for this warp
    int lbase = w * 16;                   // local slot base in smem
    #pragma unroll 1
    for (int i = 0; i < 16; i += 2) {
        int s0 = sbase + i, s1 = s0 + 1;
        int4 i0 = __ldg((const int4*)story + s0);
        int4 i1 = __ldg((const int4*)story + s1);
        float p0 = expf(__ldg(g_logit + s0) - m) * inv;
        float p1 = expf(__ldg(g_logit + s1) - m) * inv;
        float4 a0 = __ldg((const float4*)(Ct + (size_t)i0.x * E) + lane);
        float4 a1 = __ldg((const float4*)(Ct + (size_t)i0.y * E) + lane);
        float4 a2 = __ldg((const float4*)(Ct + (size_t)i0.z * E) + lane);
        float4 a3 = __ldg((const float4*)(Ct + (size_t)i0.w * E) + lane);
        float4 c0 = __ldg((const float4*)(Ct + (size_t)i1.x * E) + lane);
        float4 c1 = __ldg((const float4*)(Ct + (size_t)i1.y * E) + lane);
        float4 c2 = __ldg((const float4*)(Ct + (size_t)i1.z * E) + lane);
        float4 c3 = __ldg((const float4*)(Ct + (size_t)i1.w * E) + lane);
        float4 v0 = make_float4(a0.x + a1.x + a2.x + a3.x,
                                a0.y + a1.y + a2.y + a3.y,
                                a0.z + a1.z + a2.z + a3.z,
                                a0.w + a1.w + a2.w + a3.w);
        float4 v1 = make_float4(c0.x + c1.x + c2.x + c3.x,
                                c0.y + c1.y + c2.y + c3.y,
                                c0.z + c1.z + c2.z + c3.z,
                                c0.w + c1.w + c2.w + c3.w);
        *((float4*)&s_emb[(lbase + i) * E] + lane)     = v0;
        *((float4*)&s_emb[(lbase + i + 1) * E] + lane) = v1;
        acc.x = fmaf(p0, v0.x, acc.x); acc.y = fmaf(p0, v0.y, acc.y);
        acc.z = fmaf(p0, v0.z, acc.z); acc.w = fmaf(p0, v0.w, acc.w);
        acc.x = fmaf(p1, v1.x, acc.x); acc.y = fmaf(p1, v1.y, acc.y);
        acc.z = fmaf(p1, v1.z, acc.z); acc.w = fmaf(p1, v1.w, acc.w);
    }

    __shared__ float sred[8][128];
    *((float4*)&sred[w][lane * 4]) = acc;
    __syncthreads();
    if (t < 128) {
        float v = sred[0][t];
        #pragma unroll
        for (int ww = 1; ww < 8; ww++) v += sred[ww][t];
        atomicAdd(&g_u[b * HH + t], v);
    }

    // ---- per-batch barrier: all 16 blocks of batch b done updating g_u[b] ----
    __threadfence();          // order the g_u REDs before the counter arrive
    __syncthreads();
    if (t == 0) {
        atomicAdd(&g_cnt[cidx * B + b], 1);
        while (atomicAdd(&g_cnt[cidx * B + b], 0) < 16) { }
    }
    __syncthreads();

    // ---- phase C: next-hop logits from smem emb x updated u ----
    float4 u4;
    u4.x = __ldcg(g_u + b * HH + lane * 4 + 0);
    u4.y = __ldcg(g_u + b * HH + lane * 4 + 1);
    u4.z = __ldcg(g_u + b * HH + lane * 4 + 2);
    u4.w = __ldcg(g_u + b * HH + lane * 4 + 3);

    int len = FINAL ? __ldg(lengths + b) : 0;
    #pragma unroll 1
    for (int i = 0; i < 16; i++) {
        float4 e = *((const float4*)&s_emb[(lbase + i) * E] + lane);
        float d = e.x * u4.x + e.y * u4.y + e.z * u4.z + e.w * u4.w;
        #pragma unroll
        for (int o = 16; o; o >>= 1) d += __shfl_down_sync(FULLMASK, d, o);
        if (lane == 0) {
            int sl = slot0 + w * 16 + i;
            if (FINAL) {
                out_mask[b * S + sl] = (sl < len) ? 1.0f / (1.0f + expf(-d)) : 0.0f;
            } else {
                g_logit[b * S + sl] = d;
            }
        }
    }
}

// ---------------- host launch ----------------
extern "C" void kernel_launch(void* const* d_in, const int* in_sizes, int n_in,
                              void* d_out, int out_size)
{
    const int*   story   = (const int*)d_in[0];
    const int*   lengths = (const int*)d_in[1];
    const float* hidden  = (const float*)d_in[2];
    // d_in[3] global_pointer: unused (is_decoding == 0 path)
    const float* C       = (const float*)d_in[4];
    const float* Wm      = (const float*)d_in[5];
    const float* Wb      = (const float*)d_in[6];
    const float* W1w     = (const float*)d_in[7];
    const float* W1b     = (const float*)d_in[8];
    const float* W3w     = (const float*)d_in[9];
    const float* W3b     = (const float*)d_in[10];
    const float* W4w     = (const float*)d_in[11];
    const float* W4b     = (const float*)d_in[12];

    float* out = (float*)d_out;
    float* o_sp   = out;                       // [B,2]
    float* o_spa  = out + B * 2;               // [B,2]
    float* o_qh   = out + B * 4;               // [B,4000]
    float* o_qha  = o_qh + B * NE;             // [B,4000]
    float* o_qt   = o_qha + B * NE;            // [B,200]
    float* o_qta  = o_qt + B * NR;             // [B,200]
    float* o_mask = o_qta + B * NR;            // [B,S]

    // JAX partitionable split of key(42): k_i = threefry(key, (0, i))
    uint32_t k1a, k1b, k2a, k2b, k3a, k3b;
    threefry2x32(0u, 42u, 0u, 0u, k1a, k1b);
    threefry2x32(0u, 42u, 0u, 1u, k2a, k2b);
    threefry2x32(0u, 42u, 0u, 2u, k3a, k3b);

    const size_t TBL = (size_t)VOCAB * E;
    const int SMEM = 128 * E * sizeof(float);  // 64KB

    // opt in to >48KB dynamic smem (idempotent, safe during capture)
    cudaFuncSetAttribute(k_hop_step<false>,
                         cudaFuncAttributeMaxDynamicSharedMemorySize, SMEM);
    cudaFuncSetAttribute(k_hop_step<true>,
                         cudaFuncAttributeMaxDynamicSharedMemorySize, SMEM);

    // 1) h = hidden@Wm^T + b ; u = h ; reset barrier counters
    k_h<<<B, HH>>>(hidden, Wm, Wb);

    // 2) hop0 logit gather (C0) + all head GEMVs
    k_fused1<<<LB + HB, 256>>>(story, C,
                               W1w, W1b, W3w, W3b, W4w, W4b,
                               o_sp, o_qh, o_qt);

    // 3) softmax + update(C1) + barrier + hop1 logits, argmax piggyback
    k_hop_step<false><<<256 + 48, 256, SMEM>>>(
        story, C + TBL, 0, lengths, o_mask,
        o_sp, o_qh, o_qt, o_spa, o_qha, o_qta,
        k1a, k1b, k2a, k2b, k3a, k3b);

    // 4) softmax + update(C2) + barrier + hop2 logits + sigmoid + mask -> out
    k_hop_step<true><<<256, 256, SMEM>>>(
        story, C + 2 * TBL, 1, lengths, o_mask,
        o_sp, o_qh, o_qt, o_spa, o_qha, o_qta,
        k1a, k1b, k2a, k2b, k3a, k3b);
}

// round 8
// speedup vs baseline: 1.1756x; 1.1756x over previous
#include <cuda_runtime.h>
#include <math.h>
#include <stdint.h>

// Problem constants
#define B 16
#define S 2048
#define M 4
#define E 128
#define HH 128
#define VOCAB 100000
#define NE 4000
#define NR 200
#define FULLMASK 0xffffffffu

// hop-step geometry: 512 gather blocks, 32 per batch, 64 slots per block
#define GB 512
#define BLK_PER_BATCH 32
#define SLOTS_PER_BLK 64
#define SLOTS_PER_WARP 8

// ---------------- device scratch (no allocation allowed) ----------------
__device__ float g_h[B * HH];
__device__ float g_u[B * HH];
__device__ float g_logit[B * S];
__device__ int   g_cnt[2 * B];   // per-batch arrival counters, hop 0/1

// ---------------- threefry2x32-20 (JAX) ----------------
__host__ __device__ __forceinline__ uint32_t rotl32(uint32_t v, int d) {
    return (v << d) | (v >> (32 - d));
}

__host__ __device__ __forceinline__ void threefry2x32(
    uint32_t k0, uint32_t k1, uint32_t x0, uint32_t x1,
    uint32_t& o0, uint32_t& o1)
{
    uint32_t ks0 = k0, ks1 = k1;
    uint32_t ks2 = k0 ^ k1 ^ 0x1BD11BDAu;
    x0 += ks0; x1 += ks1;
    const int rA[4] = {13, 15, 26, 6};
    const int rB[4] = {17, 29, 16, 24};
    #pragma unroll
    for (int i = 0; i < 4; i++) { x0 += x1; x1 = rotl32(x1, rA[i]); x1 ^= x0; }
    x0 += ks1; x1 += ks2 + 1u;
    #pragma unroll
    for (int i = 0; i < 4; i++) { x0 += x1; x1 = rotl32(x1, rB[i]); x1 ^= x0; }
    x0 += ks2; x1 += ks0 + 2u;
    #pragma unroll
    for (int i = 0; i < 4; i++) { x0 += x1; x1 = rotl32(x1, rA[i]); x1 ^= x0; }
    x0 += ks0; x1 += ks1 + 3u;
    #pragma unroll
    for (int i = 0; i < 4; i++) { x0 += x1; x1 = rotl32(x1, rB[i]); x1 ^= x0; }
    x0 += ks1; x1 += ks2 + 4u;
    #pragma unroll
    for (int i = 0; i < 4; i++) { x0 += x1; x1 = rotl32(x1, rA[i]); x1 ^= x0; }
    x0 += ks2; x1 += ks0 + 5u;
    o0 = x0; o1 = x1;
}

// ---------------- h = hidden @ Wm^T + Wb ; u = h ; reset barrier counters ----
__global__ void k_h(const float* __restrict__ hidden,
                    const float* __restrict__ Wm,
                    const float* __restrict__ Wb)
{
    int b = blockIdx.x, t = threadIdx.x;
    if (t == 0) { g_cnt[b] = 0; g_cnt[B + b] = 0; }
    __shared__ float sh[HH];
    sh[t] = hidden[b * HH + t];
    __syncthreads();
    float acc = Wb[t];
    const float* w = Wm + (size_t)t * HH;
    #pragma unroll 8
    for (int k = 0; k < HH; k++) acc = fmaf(w[k], sh[k], acc);
    g_h[b * HH + t] = acc;
    g_u[b * HH + t] = acc;
}

// ============ K1: fused hop-0 logit gather  +  three head GEMVs ============
#define LB (B * S / 2 * 32 / 256)        // 2048
#define HEADW (2 + NE + NR)              // 4202 warps
#define HB ((HEADW * 32 + 255) / 256)    // 526

__global__ void k_fused1(const int* __restrict__ story,
                         const float* __restrict__ C0,
                         const float* __restrict__ W1w, const float* __restrict__ W1b,
                         const float* __restrict__ W3w, const float* __restrict__ W3b,
                         const float* __restrict__ W4w, const float* __restrict__ W4b,
                         float* __restrict__ o_sp, float* __restrict__ o_qh,
                         float* __restrict__ o_qt)
{
    if (blockIdx.x < LB) {
        int gid  = blockIdx.x * blockDim.x + threadIdx.x;
        int warp = gid >> 5, lane = gid & 31;
        int s0 = warp * 2;
        int b  = s0 >> 11;
        int4 ia = __ldg((const int4*)story + s0);
        int4 ib = __ldg((const int4*)story + s0 + 1);
        float4 a0 = __ldg((const float4*)(C0 + (size_t)ia.x * E) + lane);
        float4 a1 = __ldg((const float4*)(C0 + (size_t)ia.y * E) + lane);
        float4 a2 = __ldg((const float4*)(C0 + (size_t)ia.z * E) + lane);
        float4 a3 = __ldg((const float4*)(C0 + (size_t)ia.w * E) + lane);
        float4 b0 = __ldg((const float4*)(C0 + (size_t)ib.x * E) + lane);
        float4 b1 = __ldg((const float4*)(C0 + (size_t)ib.y * E) + lane);
        float4 b2 = __ldg((const float4*)(C0 + (size_t)ib.z * E) + lane);
        float4 b3 = __ldg((const float4*)(C0 + (size_t)ib.w * E) + lane);
        float4 u4 = *((const float4*)(g_u + b * HH) + lane);
        float sa = (a0.x + a1.x + a2.x + a3.x) * u4.x
                 + (a0.y + a1.y + a2.y + a3.y) * u4.y
                 + (a0.z + a1.z + a2.z + a3.z) * u4.z
                 + (a0.w + a1.w + a2.w + a3.w) * u4.w;
        float sb = (b0.x + b1.x + b2.x + b3.x) * u4.x
                 + (b0.y + b1.y + b2.y + b3.y) * u4.y
                 + (b0.z + b1.z + b2.z + b3.z) * u4.z
                 + (b0.w + b1.w + b2.w + b3.w) * u4.w;
        #pragma unroll
        for (int o = 16; o; o >>= 1) {
            sa += __shfl_down_sync(FULLMASK, sa, o);
            sb += __shfl_down_sync(FULLMASK, sb, o);
        }
        if (lane == 0) { g_logit[s0] = sa; g_logit[s0 + 1] = sb; }
    } else {
        int gid  = (blockIdx.x - LB) * blockDim.x + threadIdx.x;
        int w    = gid >> 5, lane = gid & 31;
        if (w >= HEADW) return;
        const float *W, *bias; float* outl; int N, n;
        if (w < 2)            { W = W1w; bias = W1b; outl = o_sp; N = 2;  n = w; }
        else if (w < 2 + NE)  { W = W3w; bias = W3b; outl = o_qh; N = NE; n = w - 2; }
        else                  { W = W4w; bias = W4b; outl = o_qt; N = NR; n = w - 2 - NE; }

        float4 w4 = __ldg((const float4*)(W + (size_t)n * HH) + lane);
        float  bs = __ldg(bias + n);
        #pragma unroll
        for (int b = 0; b < B; b++) {
            float4 h4 = *((const float4*)(g_h + b * HH) + lane);
            float s = w4.x * h4.x + w4.y * h4.y + w4.z * h4.z + w4.w * h4.w;
            #pragma unroll
            for (int o = 16; o; o >>= 1) s += __shfl_down_sync(FULLMASK, s, o);
            if (lane == 0) outl[b * N + n] = s + bs;
        }
    }
}

// ---------------- gumbel argmax one-hot body (for piggyback blocks) ----------------
__device__ __forceinline__ void argmax_body(const float* __restrict__ o_sp,
                                            const float* __restrict__ o_qh,
                                            const float* __restrict__ o_qt,
                                            float* __restrict__ a_sp,
                                            float* __restrict__ a_qh,
                                            float* __restrict__ a_qt,
                                            uint32_t k1a, uint32_t k1b,
                                            uint32_t k2a, uint32_t k2b,
                                            uint32_t k3a, uint32_t k3b,
                                            int blk2)
{
    int head = blk2 >> 4, b = blk2 & 15, t = threadIdx.x;
    const float* L; float* A; int N; uint32_t ka, kb;
    if (head == 0)      { L = o_sp; A = a_sp; N = 2;  ka = k1a; kb = k1b; }
    else if (head == 1) { L = o_qh; A = a_qh; N = NE; ka = k2a; kb = k2b; }
    else                { L = o_qt; A = a_qt; N = NR; ka = k3a; kb = k3b; }

    float bv = -INFINITY; int bi = 0x7fffffff;
    for (int i = t; i < N; i += 256) {
        int idx = b * N + i;
        float logit = __ldg(L + idx);
        uint32_t o0, o1;
        threefry2x32(ka, kb, 0u, (uint32_t)idx, o0, o1);
        uint32_t bits = o0 ^ o1;
        float u = __uint_as_float((bits >> 9) | 0x3F800000u) - 1.0f;
        float v = fmaxf(1e-10f, u + 1e-10f);
        float g = -logf(-logf(v));
        float nv = logit + g;
        if (nv > bv || (nv == bv && i < bi)) { bv = nv; bi = i; }
    }
    __shared__ float sv[256];
    __shared__ int   si[256];
    sv[t] = bv; si[t] = bi;
    __syncthreads();
    for (int o = 128; o; o >>= 1) {
        if (t < o) {
            if (sv[t + o] > sv[t] || (sv[t + o] == sv[t] && si[t + o] < si[t])) {
                sv[t] = sv[t + o]; si[t] = si[t + o];
            }
        }
        __syncthreads();
    }
    int best = si[0];
    float* out = A + b * N;
    for (int i = t; i < N; i += 256) out[i] = (i == best) ? 1.0f : 0.0f;
}

// ============ hop step: softmax + gather + u update + batch barrier + logits ======
// GB=512 gather blocks: 32 per batch, 64 slots each (warp owns 8 slots).
// Slot embeddings parked in 32KB dynamic smem; after a per-batch arrival barrier
// (32 blocks, all co-resident: 6 blocks/SM occupancy ceiling -> 888 >= 512),
// next-hop logits are computed from smem against the freshly-updated u (__ldcg).
// FINAL=false also carries 48 argmax blocks [GB, GB+48).
template<bool FINAL>
__global__ void __launch_bounds__(256)
k_hop_step(const int* __restrict__ story,
           const float* __restrict__ Ct,
           int cidx,
           const int* __restrict__ lengths,
           float* __restrict__ out_mask,
           const float* __restrict__ o_sp, const float* __restrict__ o_qh,
           const float* __restrict__ o_qt,
           float* __restrict__ a_sp, float* __restrict__ a_qh,
           float* __restrict__ a_qt,
           uint32_t k1a, uint32_t k1b, uint32_t k2a, uint32_t k2b,
           uint32_t k3a, uint32_t k3b)
{
    extern __shared__ float s_emb[];   // 64 slots x 128 floats = 32KB

    if (!FINAL && blockIdx.x >= GB) {
        argmax_body(o_sp, o_qh, o_qt, a_sp, a_qh, a_qt,
                    k1a, k1b, k2a, k2b, k3a, k3b, blockIdx.x - GB);
        return;
    }

    int blk = blockIdx.x;
    int b   = blk / BLK_PER_BATCH;
    int slot0 = (blk % BLK_PER_BATCH) * SLOTS_PER_BLK;
    int t = threadIdx.x, lane = t & 31, w = t >> 5;

    // ---- phase A: softmax stats over this batch's logits ----
    const float* l = g_logit + b * S;
    __shared__ float red[256];
    float m = -INFINITY;
    for (int i = t; i < S; i += 256) m = fmaxf(m, __ldg(l + i));
    red[t] = m; __syncthreads();
    #pragma unroll
    for (int o = 128; o; o >>= 1) { if (t < o) red[t] = fmaxf(red[t], red[t + o]); __syncthreads(); }
    m = red[0]; __syncthreads();
    float sum = 0.f;
    for (int i = t; i < S; i += 256) sum += expf(__ldg(l + i) - m);
    red[t] = sum; __syncthreads();
    #pragma unroll
    for (int o = 128; o; o >>= 1) { if (t < o) red[t] += red[t + o]; __syncthreads(); }
    float inv = 1.0f / red[0];
    __syncthreads();

    // ---- phase B: gather + weighted accumulate + park emb in smem ----
    float4 acc = make_float4(0.f, 0.f, 0.f, 0.f);
    int sbase = b * S + slot0 + w * SLOTS_PER_WARP;
    int lbase = w * SLOTS_PER_WARP;
    #pragma unroll 1
    for (int i = 0; i < SLOTS_PER_WARP; i += 2) {
        int s0 = sbase + i, s1 = s0 + 1;
        int4 i0 = __ldg((const int4*)story + s0);
        int4 i1 = __ldg((const int4*)story + s1);
        float p0 = expf(__ldg(g_logit + s0) - m) * inv;
        float p1 = expf(__ldg(g_logit + s1) - m) * inv;
        float4 a0 = __ldg((const float4*)(Ct + (size_t)i0.x * E) + lane);
        float4 a1 = __ldg((const float4*)(Ct + (size_t)i0.y * E) + lane);
        float4 a2 = __ldg((const float4*)(Ct + (size_t)i0.z * E) + lane);
        float4 a3 = __ldg((const float4*)(Ct + (size_t)i0.w * E) + lane);
        float4 c0 = __ldg((const float4*)(Ct + (size_t)i1.x * E) + lane);
        float4 c1 = __ldg((const float4*)(Ct + (size_t)i1.y * E) + lane);
        float4 c2 = __ldg((const float4*)(Ct + (size_t)i1.z * E) + lane);
        float4 c3 = __ldg((const float4*)(Ct + (size_t)i1.w * E) + lane);
        float4 v0 = make_float4(a0.x + a1.x + a2.x + a3.x,
                                a0.y + a1.y + a2.y + a3.y,
                                a0.z + a1.z + a2.z + a3.z,
                                a0.w + a1.w + a2.w + a3.w);
        float4 v1 = make_float4(c0.x + c1.x + c2.x + c3.x,
                                c0.y + c1.y + c2.y + c3.y,
                                c0.z + c1.z + c2.z + c3.z,
                                c0.w + c1.w + c2.w + c3.w);
        *((float4*)&s_emb[(lbase + i) * E] + lane)     = v0;
        *((float4*)&s_emb[(lbase + i + 1) * E] + lane) = v1;
        acc.x = fmaf(p0, v0.x, acc.x); acc.y = fmaf(p0, v0.y, acc.y);
        acc.z = fmaf(p0, v0.z, acc.z); acc.w = fmaf(p0, v0.w, acc.w);
        acc.x = fmaf(p1, v1.x, acc.x); acc.y = fmaf(p1, v1.y, acc.y);
        acc.z = fmaf(p1, v1.z, acc.z); acc.w = fmaf(p1, v1.w, acc.w);
    }

    __shared__ float sred[8][128];
    *((float4*)&sred[w][lane * 4]) = acc;
    __syncthreads();
    if (t < 128) {
        float v = sred[0][t];
        #pragma unroll
        for (int ww = 1; ww < 8; ww++) v += sred[ww][t];
        atomicAdd(&g_u[b * HH + t], v);
    }

    // ---- per-batch barrier: all 32 blocks of batch b done updating g_u[b] ----
    __threadfence();          // order the g_u REDs before the counter arrive
    __syncthreads();
    if (t == 0) {
        atomicAdd(&g_cnt[cidx * B + b], 1);
        while (atomicAdd(&g_cnt[cidx * B + b], 0) < BLK_PER_BATCH) { }
    }
    __syncthreads();

    // ---- phase C: next-hop logits from smem emb x updated u ----
    float4 u4;
    u4.x = __ldcg(g_u + b * HH + lane * 4 + 0);
    u4.y = __ldcg(g_u + b * HH + lane * 4 + 1);
    u4.z = __ldcg(g_u + b * HH + lane * 4 + 2);
    u4.w = __ldcg(g_u + b * HH + lane * 4 + 3);

    int len = FINAL ? __ldg(lengths + b) : 0;
    #pragma unroll 1
    for (int i = 0; i < SLOTS_PER_WARP; i++) {
        float4 e = *((const float4*)&s_emb[(lbase + i) * E] + lane);
        float d = e.x * u4.x + e.y * u4.y + e.z * u4.z + e.w * u4.w;
        #pragma unroll
        for (int o = 16; o; o >>= 1) d += __shfl_down_sync(FULLMASK, d, o);
        if (lane == 0) {
            int sl = slot0 + w * SLOTS_PER_WARP + i;
            if (FINAL) {
                out_mask[b * S + sl] = (sl < len) ? 1.0f / (1.0f + expf(-d)) : 0.0f;
            } else {
                g_logit[b * S + sl] = d;
            }
        }
    }
}

// ---------------- host launch ----------------
extern "C" void kernel_launch(void* const* d_in, const int* in_sizes, int n_in,
                              void* d_out, int out_size)
{
    const int*   story   = (const int*)d_in[0];
    const int*   lengths = (const int*)d_in[1];
    const float* hidden  = (const float*)d_in[2];
    // d_in[3] global_pointer: unused (is_decoding == 0 path)
    const float* C       = (const float*)d_in[4];
    const float* Wm      = (const float*)d_in[5];
    const float* Wb      = (const float*)d_in[6];
    const float* W1w     = (const float*)d_in[7];
    const float* W1b     = (const float*)d_in[8];
    const float* W3w     = (const float*)d_in[9];
    const float* W3b     = (const float*)d_in[10];
    const float* W4w     = (const float*)d_in[11];
    const float* W4b     = (const float*)d_in[12];

    float* out = (float*)d_out;
    float* o_sp   = out;                       // [B,2]
    float* o_spa  = out + B * 2;               // [B,2]
    float* o_qh   = out + B * 4;               // [B,4000]
    float* o_qha  = o_qh + B * NE;             // [B,4000]
    float* o_qt   = o_qha + B * NE;            // [B,200]
    float* o_qta  = o_qt + B * NR;             // [B,200]
    float* o_mask = o_qta + B * NR;            // [B,S]

    // JAX partitionable split of key(42): k_i = threefry(key, (0, i))
    uint32_t k1a, k1b, k2a, k2b, k3a, k3b;
    threefry2x32(0u, 42u, 0u, 0u, k1a, k1b);
    threefry2x32(0u, 42u, 0u, 1u, k2a, k2b);
    threefry2x32(0u, 42u, 0u, 2u, k3a, k3b);

    const size_t TBL = (size_t)VOCAB * E;
    const int SMEM = SLOTS_PER_BLK * E * sizeof(float);  // 32KB (<=48KB default)

    // 1) h = hidden@Wm^T + b ; u = h ; reset barrier counters
    k_h<<<B, HH>>>(hidden, Wm, Wb);

    // 2) hop0 logit gather (C0) + all head GEMVs
    k_fused1<<<LB + HB, 256>>>(story, C,
                               W1w, W1b, W3w, W3b, W4w, W4b,
                               o_sp, o_qh, o_qt);

    // 3) softmax + update(C1) + barrier + hop1 logits, argmax piggyback
    k_hop_step<false><<<GB + 48, 256, SMEM>>>(
        story, C + TBL, 0, lengths, o_mask,
        o_sp, o_qh, o_qt, o_spa, o_qha, o_qta,
        k1a, k1b, k2a, k2b, k3a, k3b);

    // 4) softmax + update(C2) + barrier + hop2 logits + sigmoid + mask -> out
    k_hop_step<true><<<GB, 256, SMEM>>>(
        story, C + 2 * TBL, 1, lengths, o_mask,
        o_sp, o_qh, o_qt, o_spa, o_qha, o_qta,
        k1a, k1b, k2a, k2b, k3a, k3b);
}

// round 9
// speedup vs baseline: 1.6179x; 1.3763x over previous
#include <cuda_runtime.h>
#include <math.h>
#include <stdint.h>

// Problem constants
#define B 16
#define S 2048
#define M 4
#define E 128
#define HH 128
#define VOCAB 100000
#define NE 4000
#define NR 200
#define FULLMASK 0xffffffffu

// mega-kernel geometry
#define GB 512            // gather blocks (barrier participants)
#define BPB 32            // gather blocks per batch
#define SPB 64            // slots per gather block
#define SPW 8             // slots per warp
#define HEADW (2 + NE + NR)               // 4202 head warps
#define HB ((HEADW * 32 + 255) / 256)     // 526 head blocks
#define AB 48                             // argmax blocks

// ---------------- device scratch (no allocation allowed) ----------------
__device__ float g_h[B * HH];
__device__ float g_u[B * HH];
__device__ float g_logit[B * S];
__device__ int   g_cnt[4 * B];     // per-batch barrier counters x 4 rounds
__device__ int   g_headcnt;        // head-block completion counter

// ---------------- threefry2x32-20 (JAX) ----------------
__host__ __device__ __forceinline__ uint32_t rotl32(uint32_t v, int d) {
    return (v << d) | (v >> (32 - d));
}

__host__ __device__ __forceinline__ void threefry2x32(
    uint32_t k0, uint32_t k1, uint32_t x0, uint32_t x1,
    uint32_t& o0, uint32_t& o1)
{
    uint32_t ks0 = k0, ks1 = k1;
    uint32_t ks2 = k0 ^ k1 ^ 0x1BD11BDAu;
    x0 += ks0; x1 += ks1;
    const int rA[4] = {13, 15, 26, 6};
    const int rB[4] = {17, 29, 16, 24};
    #pragma unroll
    for (int i = 0; i < 4; i++) { x0 += x1; x1 = rotl32(x1, rA[i]); x1 ^= x0; }
    x0 += ks1; x1 += ks2 + 1u;
    #pragma unroll
    for (int i = 0; i < 4; i++) { x0 += x1; x1 = rotl32(x1, rB[i]); x1 ^= x0; }
    x0 += ks2; x1 += ks0 + 2u;
    #pragma unroll
    for (int i = 0; i < 4; i++) { x0 += x1; x1 = rotl32(x1, rA[i]); x1 ^= x0; }
    x0 += ks0; x1 += ks1 + 3u;
    #pragma unroll
    for (int i = 0; i < 4; i++) { x0 += x1; x1 = rotl32(x1, rB[i]); x1 ^= x0; }
    x0 += ks1; x1 += ks2 + 4u;
    #pragma unroll
    for (int i = 0; i < 4; i++) { x0 += x1; x1 = rotl32(x1, rA[i]); x1 ^= x0; }
    x0 += ks2; x1 += ks0 + 5u;
    o0 = x0; o1 = x1;
}

// ---------------- h = hidden @ Wm^T + Wb ; u = h ; reset all counters ----
__global__ void k_h(const float* __restrict__ hidden,
                    const float* __restrict__ Wm,
                    const float* __restrict__ Wb)
{
    int b = blockIdx.x, t = threadIdx.x;
    if (t == 0) {
        g_cnt[b] = 0; g_cnt[B + b] = 0; g_cnt[2 * B + b] = 0; g_cnt[3 * B + b] = 0;
        if (b == 0) g_headcnt = 0;
    }
    __shared__ float sh[HH];
    sh[t] = hidden[b * HH + t];
    __syncthreads();
    float acc = Wb[t];
    const float* w = Wm + (size_t)t * HH;
    #pragma unroll 8
    for (int k = 0; k < HH; k++) acc = fmaf(w[k], sh[k], acc);
    g_h[b * HH + t] = acc;
    g_u[b * HH + t] = acc;
}

// ================================ MEGA KERNEL ================================
__global__ void __launch_bounds__(256, 4)
k_mega(const int* __restrict__ story,
       const float* __restrict__ C,
       const int* __restrict__ lengths,
       const float* __restrict__ W1w, const float* __restrict__ W1b,
       const float* __restrict__ W3w, const float* __restrict__ W3b,
       const float* __restrict__ W4w, const float* __restrict__ W4b,
       float* __restrict__ o_sp, float* __restrict__ o_qh, float* __restrict__ o_qt,
       float* __restrict__ a_sp, float* __restrict__ a_qh, float* __restrict__ a_qt,
       float* __restrict__ o_mask,
       uint32_t k1a, uint32_t k1b, uint32_t k2a, uint32_t k2b,
       uint32_t k3a, uint32_t k3b)
{
    extern __shared__ float s_emb[];     // SPB x E floats = 32KB
    __shared__ float s_logit[SPB];
    __shared__ float red[256];
    __shared__ float sred[8][128];

    const size_t TBL = (size_t)VOCAB * E;
    int bid = blockIdx.x;
    int t = threadIdx.x, lane = t & 31, w = t >> 5;

    // ---------------- head-GEMV blocks ----------------
    if (bid >= GB && bid < GB + HB) {
        int gid = (bid - GB) * 256 + t;
        int hw  = gid >> 5;
        if (hw < HEADW) {
            const float *W, *bias; float* outl; int N, n;
            if (hw < 2)           { W = W1w; bias = W1b; outl = o_sp; N = 2;  n = hw; }
            else if (hw < 2 + NE) { W = W3w; bias = W3b; outl = o_qh; N = NE; n = hw - 2; }
            else                  { W = W4w; bias = W4b; outl = o_qt; N = NR; n = hw - 2 - NE; }
            float4 w4 = __ldg((const float4*)(W + (size_t)n * HH) + lane);
            float  bs = __ldg(bias + n);
            #pragma unroll
            for (int b = 0; b < B; b++) {
                float4 h4 = __ldg((const float4*)(g_h + b * HH) + lane);
                float s = w4.x * h4.x + w4.y * h4.y + w4.z * h4.z + w4.w * h4.w;
                #pragma unroll
                for (int o = 16; o; o >>= 1) s += __shfl_down_sync(FULLMASK, s, o);
                if (lane == 0) outl[b * N + n] = s + bs;
            }
        }
        __threadfence();
        __syncthreads();
        if (t == 0) atomicAdd(&g_headcnt, 1);
        return;
    }

    // ---------------- argmax blocks (spin on head completion) ----------------
    if (bid >= GB + HB) {
        if (t == 0) { while (atomicAdd(&g_headcnt, 0) < HB) { } }
        __syncthreads();
        int blk2 = bid - GB - HB;
        int head = blk2 >> 4, b = blk2 & 15;
        const float* L; float* A; int N; uint32_t ka, kb;
        if (head == 0)      { L = o_sp; A = a_sp; N = 2;  ka = k1a; kb = k1b; }
        else if (head == 1) { L = o_qh; A = a_qh; N = NE; ka = k2a; kb = k2b; }
        else                { L = o_qt; A = a_qt; N = NR; ka = k3a; kb = k3b; }

        float bv = -INFINITY; int bi = 0x7fffffff;
        for (int i = t; i < N; i += 256) {
            int idx = b * N + i;
            float logit = __ldcg(L + idx);   // produced in this kernel -> bypass L1
            uint32_t o0, o1;
            threefry2x32(ka, kb, 0u, (uint32_t)idx, o0, o1);
            uint32_t bits = o0 ^ o1;
            float u = __uint_as_float((bits >> 9) | 0x3F800000u) - 1.0f;
            float v = fmaxf(1e-10f, u + 1e-10f);
            float g = -logf(-logf(v));
            float nv = logit + g;
            if (nv > bv || (nv == bv && i < bi)) { bv = nv; bi = i; }
        }
        float* sv = red;
        int*   si = (int*)&sred[0][0];
        sv[t] = bv; si[t] = bi;
        __syncthreads();
        for (int o = 128; o; o >>= 1) {
            if (t < o) {
                if (sv[t + o] > sv[t] || (sv[t + o] == sv[t] && si[t + o] < si[t])) {
                    sv[t] = sv[t + o]; si[t] = si[t + o];
                }
            }
            __syncthreads();
        }
        int best = si[0];
        float* out = A + b * N;
        for (int i = t; i < N; i += 256) out[i] = (i == best) ? 1.0f : 0.0f;
        return;
    }

    // ======================= gather blocks: full hop chain =======================
    int b     = bid / BPB;
    int slot0 = (bid % BPB) * SPB;
    int sbase = b * S + slot0 + w * SPW;
    int lbase = w * SPW;
    const float* u_b = g_u + b * HH;
    const float* lrow = g_logit + b * S;

    // ---- hop 0: gather C0, logits0 = emb0 . u0 (emb0 single-use, no smem) ----
    {
        float4 u4 = __ldg((const float4*)u_b + lane);   // u0 = h, fresh from k_h
        #pragma unroll 1
        for (int i = 0; i < SPW; i += 2) {
            int s0 = sbase + i, s1 = s0 + 1;
            int4 i0 = __ldg((const int4*)story + s0);
            int4 i1 = __ldg((const int4*)story + s1);
            float4 a0 = __ldg((const float4*)(C + (size_t)i0.x * E) + lane);
            float4 a1 = __ldg((const float4*)(C + (size_t)i0.y * E) + lane);
            float4 a2 = __ldg((const float4*)(C + (size_t)i0.z * E) + lane);
            float4 a3 = __ldg((const float4*)(C + (size_t)i0.w * E) + lane);
            float4 c0 = __ldg((const float4*)(C + (size_t)i1.x * E) + lane);
            float4 c1 = __ldg((const float4*)(C + (size_t)i1.y * E) + lane);
            float4 c2 = __ldg((const float4*)(C + (size_t)i1.z * E) + lane);
            float4 c3 = __ldg((const float4*)(C + (size_t)i1.w * E) + lane);
            float sa = (a0.x + a1.x + a2.x + a3.x) * u4.x
                     + (a0.y + a1.y + a2.y + a3.y) * u4.y
                     + (a0.z + a1.z + a2.z + a3.z) * u4.z
                     + (a0.w + a1.w + a2.w + a3.w) * u4.w;
            float sb = (c0.x + c1.x + c2.x + c3.x) * u4.x
                     + (c0.y + c1.y + c2.y + c3.y) * u4.y
                     + (c0.z + c1.z + c2.z + c3.z) * u4.z
                     + (c0.w + c1.w + c2.w + c3.w) * u4.w;
            #pragma unroll
            for (int o = 16; o; o >>= 1) {
                sa += __shfl_down_sync(FULLMASK, sa, o);
                sb += __shfl_down_sync(FULLMASK, sb, o);
            }
            if (lane == 0) {
                g_logit[s0] = sa; g_logit[s1] = sb;
                s_logit[lbase + i] = sa; s_logit[lbase + i + 1] = sb;
            }
        }
    }
    __threadfence(); __syncthreads();
    if (t == 0) { atomicAdd(&g_cnt[b], 1); while (atomicAdd(&g_cnt[b], 0) < BPB) { } }
    __syncthreads();

    // ---- softmax0 stats over the batch row (ldcg: same-kernel data) ----
    float m0, inv0;
    {
        float mm = -INFINITY;
        for (int i = t; i < S / 4; i += 256) {
            float4 v = __ldcg((const float4*)lrow + i);
            mm = fmaxf(fmaxf(mm, fmaxf(v.x, v.y)), fmaxf(v.z, v.w));
        }
        red[t] = mm; __syncthreads();
        #pragma unroll
        for (int o = 128; o; o >>= 1) { if (t < o) red[t] = fmaxf(red[t], red[t + o]); __syncthreads(); }
        mm = red[0]; __syncthreads();
        float s = 0.f;
        for (int i = t; i < S / 4; i += 256) {
            float4 v = __ldcg((const float4*)lrow + i);
            s += expf(v.x - mm) + expf(v.y - mm) + expf(v.z - mm) + expf(v.w - mm);
        }
        red[t] = s; __syncthreads();
        #pragma unroll
        for (int o = 128; o; o >>= 1) { if (t < o) red[t] += red[t + o]; __syncthreads(); }
        m0 = mm; inv0 = 1.0f / red[0];
        __syncthreads();
    }

    // ---- hop 1: gather C1 -> smem emb, u += sum p0 * emb ----
    {
        const float* Ct = C + TBL;
        float4 acc = make_float4(0.f, 0.f, 0.f, 0.f);
        #pragma unroll 1
        for (int i = 0; i < SPW; i += 2) {
            int s0 = sbase + i, s1 = s0 + 1;
            int4 i0 = __ldg((const int4*)story + s0);
            int4 i1 = __ldg((const int4*)story + s1);
            float p0 = expf(s_logit[lbase + i] - m0) * inv0;
            float p1 = expf(s_logit[lbase + i + 1] - m0) * inv0;
            float4 a0 = __ldg((const float4*)(Ct + (size_t)i0.x * E) + lane);
            float4 a1 = __ldg((const float4*)(Ct + (size_t)i0.y * E) + lane);
            float4 a2 = __ldg((const float4*)(Ct + (size_t)i0.z * E) + lane);
            float4 a3 = __ldg((const float4*)(Ct + (size_t)i0.w * E) + lane);
            float4 c0 = __ldg((const float4*)(Ct + (size_t)i1.x * E) + lane);
            float4 c1 = __ldg((const float4*)(Ct + (size_t)i1.y * E) + lane);
            float4 c2 = __ldg((const float4*)(Ct + (size_t)i1.z * E) + lane);
            float4 c3 = __ldg((const float4*)(Ct + (size_t)i1.w * E) + lane);
            float4 v0 = make_float4(a0.x + a1.x + a2.x + a3.x, a0.y + a1.y + a2.y + a3.y,
                                    a0.z + a1.z + a2.z + a3.z, a0.w + a1.w + a2.w + a3.w);
            float4 v1 = make_float4(c0.x + c1.x + c2.x + c3.x, c0.y + c1.y + c2.y + c3.y,
                                    c0.z + c1.z + c2.z + c3.z, c0.w + c1.w + c2.w + c3.w);
            *((float4*)&s_emb[(lbase + i) * E] + lane)     = v0;
            *((float4*)&s_emb[(lbase + i + 1) * E] + lane) = v1;
            acc.x = fmaf(p0, v0.x, acc.x); acc.y = fmaf(p0, v0.y, acc.y);
            acc.z = fmaf(p0, v0.z, acc.z); acc.w = fmaf(p0, v0.w, acc.w);
            acc.x = fmaf(p1, v1.x, acc.x); acc.y = fmaf(p1, v1.y, acc.y);
            acc.z = fmaf(p1, v1.z, acc.z); acc.w = fmaf(p1, v1.w, acc.w);
        }
        *((float4*)&sred[w][lane * 4]) = acc;
        __syncthreads();
        if (t < 128) {
            float v = sred[0][t];
            #pragma unroll
            for (int ww = 1; ww < 8; ww++) v += sred[ww][t];
            atomicAdd(&g_u[b * HH + t], v);
        }
    }
    __threadfence(); __syncthreads();
    if (t == 0) { atomicAdd(&g_cnt[B + b], 1); while (atomicAdd(&g_cnt[B + b], 0) < BPB) { } }
    __syncthreads();

    // ---- logits1 = emb1 . u1 (u1 via ldcg) ----
    {
        float4 u4 = __ldcg((const float4*)u_b + lane);
        #pragma unroll 1
        for (int i = 0; i < SPW; i++) {
            float4 e = *((const float4*)&s_emb[(lbase + i) * E] + lane);
            float d = e.x * u4.x + e.y * u4.y + e.z * u4.z + e.w * u4.w;
            #pragma unroll
            for (int o = 16; o; o >>= 1) d += __shfl_down_sync(FULLMASK, d, o);
            if (lane == 0) {
                g_logit[sbase + i] = d;
                s_logit[lbase + i] = d;
            }
        }
    }
    __threadfence(); __syncthreads();
    if (t == 0) { atomicAdd(&g_cnt[2 * B + b], 1); while (atomicAdd(&g_cnt[2 * B + b], 0) < BPB) { } }
    __syncthreads();

    // ---- softmax1 stats ----
    float m1, inv1;
    {
        float mm = -INFINITY;
        for (int i = t; i < S / 4; i += 256) {
            float4 v = __ldcg((const float4*)lrow + i);
            mm = fmaxf(fmaxf(mm, fmaxf(v.x, v.y)), fmaxf(v.z, v.w));
        }
        red[t] = mm; __syncthreads();
        #pragma unroll
        for (int o = 128; o; o >>= 1) { if (t < o) red[t] = fmaxf(red[t], red[t + o]); __syncthreads(); }
        mm = red[0]; __syncthreads();
        float s = 0.f;
        for (int i = t; i < S / 4; i += 256) {
            float4 v = __ldcg((const float4*)lrow + i);
            s += expf(v.x - mm) + expf(v.y - mm) + expf(v.z - mm) + expf(v.w - mm);
        }
        red[t] = s; __syncthreads();
        #pragma unroll
        for (int o = 128; o; o >>= 1) { if (t < o) red[t] += red[t + o]; __syncthreads(); }
        m1 = mm; inv1 = 1.0f / red[0];
        __syncthreads();
    }

    // ---- hop 2: gather C2 -> smem emb (overwrite), u += sum p1 * emb ----
    {
        const float* Ct = C + 2 * TBL;
        float4 acc = make_float4(0.f, 0.f, 0.f, 0.f);
        #pragma unroll 1
        for (int i = 0; i < SPW; i += 2) {
            int s0 = sbase + i, s1 = s0 + 1;
            int4 i0 = __ldg((const int4*)story + s0);
            int4 i1 = __ldg((const int4*)story + s1);
            float p0 = expf(s_logit[lbase + i] - m1) * inv1;
            float p1 = expf(s_logit[lbase + i + 1] - m1) * inv1;
            float4 a0 = __ldg((const float4*)(Ct + (size_t)i0.x * E) + lane);
            float4 a1 = __ldg((const float4*)(Ct + (size_t)i0.y * E) + lane);
            float4 a2 = __ldg((const float4*)(Ct + (size_t)i0.z * E) + lane);
            float4 a3 = __ldg((const float4*)(Ct + (size_t)i0.w * E) + lane);
            float4 c0 = __ldg((const float4*)(Ct + (size_t)i1.x * E) + lane);
            float4 c1 = __ldg((const float4*)(Ct + (size_t)i1.y * E) + lane);
            float4 c2 = __ldg((const float4*)(Ct + (size_t)i1.z * E) + lane);
            float4 c3 = __ldg((const float4*)(Ct + (size_t)i1.w * E) + lane);
            float4 v0 = make_float4(a0.x + a1.x + a2.x + a3.x, a0.y + a1.y + a2.y + a3.y,
                                    a0.z + a1.z + a2.z + a3.z, a0.w + a1.w + a2.w + a3.w);
            float4 v1 = make_float4(c0.x + c1.x + c2.x + c3.x, c0.y + c1.y + c2.y + c3.y,
                                    c0.z + c1.z + c2.z + c3.z, c0.w + c1.w + c2.w + c3.w);
            *((float4*)&s_emb[(lbase + i) * E] + lane)     = v0;
            *((float4*)&s_emb[(lbase + i + 1) * E] + lane) = v1;
            acc.x = fmaf(p0, v0.x, acc.x); acc.y = fmaf(p0, v0.y, acc.y);
            acc.z = fmaf(p0, v0.z, acc.z); acc.w = fmaf(p0, v0.w, acc.w);
            acc.x = fmaf(p1, v1.x, acc.x); acc.y = fmaf(p1, v1.y, acc.y);
            acc.z = fmaf(p1, v1.z, acc.z); acc.w = fmaf(p1, v1.w, acc.w);
        }
        *((float4*)&sred[w][lane * 4]) = acc;
        __syncthreads();
        if (t < 128) {
            float v = sred[0][t];
            #pragma unroll
            for (int ww = 1; ww < 8; ww++) v += sred[ww][t];
            atomicAdd(&g_u[b * HH + t], v);
        }
    }
    __threadfence(); __syncthreads();
    if (t == 0) { atomicAdd(&g_cnt[3 * B + b], 1); while (atomicAdd(&g_cnt[3 * B + b], 0) < BPB) { } }
    __syncthreads();

    // ---- final: logits2 = emb2 . u2 -> sigmoid + length mask -> out ----
    {
        float4 u4 = __ldcg((const float4*)u_b + lane);
        int len = __ldg(lengths + b);
        #pragma unroll 1
        for (int i = 0; i < SPW; i++) {
            float4 e = *((const float4*)&s_emb[(lbase + i) * E] + lane);
            float d = e.x * u4.x + e.y * u4.y + e.z * u4.z + e.w * u4.w;
            #pragma unroll
            for (int o = 16; o; o >>= 1) d += __shfl_down_sync(FULLMASK, d, o);
            if (lane == 0) {
                int sl = slot0 + w * SPW + i;
                o_mask[b * S + sl] = (sl < len) ? 1.0f / (1.0f + expf(-d)) : 0.0f;
            }
        }
    }
}

// ---------------- host launch ----------------
extern "C" void kernel_launch(void* const* d_in, const int* in_sizes, int n_in,
                              void* d_out, int out_size)
{
    const int*   story   = (const int*)d_in[0];
    const int*   lengths = (const int*)d_in[1];
    const float* hidden  = (const float*)d_in[2];
    // d_in[3] global_pointer: unused (is_decoding == 0 path)
    const float* C       = (const float*)d_in[4];
    const float* Wm      = (const float*)d_in[5];
    const float* Wb      = (const float*)d_in[6];
    const float* W1w     = (const float*)d_in[7];
    const float* W1b     = (const float*)d_in[8];
    const float* W3w     = (const float*)d_in[9];
    const float* W3b     = (const float*)d_in[10];
    const float* W4w     = (const float*)d_in[11];
    const float* W4b     = (const float*)d_in[12];

    float* out = (float*)d_out;
    float* o_sp   = out;                       // [B,2]
    float* o_spa  = out + B * 2;               // [B,2]
    float* o_qh   = out + B * 4;               // [B,4000]
    float* o_qha  = o_qh + B * NE;             // [B,4000]
    float* o_qt   = o_qha + B * NE;            // [B,200]
    float* o_qta  = o_qt + B * NR;             // [B,200]
    float* o_mask = o_qta + B * NR;            // [B,S]

    // JAX partitionable split of key(42): k_i = threefry(key, (0, i))
    uint32_t k1a, k1b, k2a, k2b, k3a, k3b;
    threefry2x32(0u, 42u, 0u, 0u, k1a, k1b);
    threefry2x32(0u, 42u, 0u, 1u, k2a, k2b);
    threefry2x32(0u, 42u, 0u, 2u, k3a, k3b);

    const int SMEM = SPB * E * sizeof(float);  // 32KB dynamic

    // 1) h = hidden@Wm^T + b ; u = h ; reset all barrier counters
    k_h<<<B, HH>>>(hidden, Wm, Wb);

    // 2) everything else: hop chain (512 barrier blocks) + heads + argmax
    k_mega<<<GB + HB + AB, 256, SMEM>>>(
        story, C, lengths,
        W1w, W1b, W3w, W3b, W4w, W4b,
        o_sp, o_qh, o_qt, o_spa, o_qha, o_qta, o_mask,
        k1a, k1b, k2a, k2b, k3a, k3b);
}

// round 10
// speedup vs baseline: 1.9390x; 1.1985x over previous
#include <cuda_runtime.h>
#include <math.h>
#include <stdint.h>

// Problem constants
#define B 16
#define S 2048
#define M 4
#define E 128
#define HH 128
#define VOCAB 100000
#define NE 4000
#define NR 200
#define FULLMASK 0xffffffffu

// mega-kernel geometry
#define GB 512            // gather blocks (barrier participants)
#define BPB 32            // gather blocks per batch
#define SPB 64            // slots per gather block
#define SPW 8             // slots per warp
#define HEADW (2 + NE + NR)               // 4202 head warps
#define HB ((HEADW * 32 + 255) / 256)     // 526 head blocks
#define AB 48                             // argmax blocks

// ---------------- device scratch (no allocation allowed) ----------------
__device__ float  g_h[B * HH];
__device__ float  g_u[B * HH];
__device__ float2 g_stats[2][B * BPB];  // per-block softmax partials (m, sum)
__device__ int    g_cnt[4 * B];         // per-batch barrier counters x 4 rounds
__device__ int    g_headcnt;            // head-block completion counter

// ---------------- threefry2x32-20 (JAX) ----------------
__host__ __device__ __forceinline__ uint32_t rotl32(uint32_t v, int d) {
    return (v << d) | (v >> (32 - d));
}

__host__ __device__ __forceinline__ void threefry2x32(
    uint32_t k0, uint32_t k1, uint32_t x0, uint32_t x1,
    uint32_t& o0, uint32_t& o1)
{
    uint32_t ks0 = k0, ks1 = k1;
    uint32_t ks2 = k0 ^ k1 ^ 0x1BD11BDAu;
    x0 += ks0; x1 += ks1;
    const int rA[4] = {13, 15, 26, 6};
    const int rB[4] = {17, 29, 16, 24};
    #pragma unroll
    for (int i = 0; i < 4; i++) { x0 += x1; x1 = rotl32(x1, rA[i]); x1 ^= x0; }
    x0 += ks1; x1 += ks2 + 1u;
    #pragma unroll
    for (int i = 0; i < 4; i++) { x0 += x1; x1 = rotl32(x1, rB[i]); x1 ^= x0; }
    x0 += ks2; x1 += ks0 + 2u;
    #pragma unroll
    for (int i = 0; i < 4; i++) { x0 += x1; x1 = rotl32(x1, rA[i]); x1 ^= x0; }
    x0 += ks0; x1 += ks1 + 3u;
    #pragma unroll
    for (int i = 0; i < 4; i++) { x0 += x1; x1 = rotl32(x1, rB[i]); x1 ^= x0; }
    x0 += ks1; x1 += ks2 + 4u;
    #pragma unroll
    for (int i = 0; i < 4; i++) { x0 += x1; x1 = rotl32(x1, rA[i]); x1 ^= x0; }
    x0 += ks2; x1 += ks0 + 5u;
    o0 = x0; o1 = x1;
}

// ---------------- h = hidden @ Wm^T + Wb ; u = h ; reset counters ----------
// warp per output element: 2048 warps = 256 blocks x 8 warps
__global__ void k_h(const float* __restrict__ hidden,
                    const float* __restrict__ Wm,
                    const float* __restrict__ Wb)
{
    int t = threadIdx.x, lane = t & 31;
    if (blockIdx.x == 0) {
        if (t < 4 * B) g_cnt[t] = 0;
        if (t == 4 * B) g_headcnt = 0;
    }
    int gw   = blockIdx.x * 8 + (t >> 5);   // 0..2047
    int b    = gw >> 7;
    int row  = gw & 127;
    float4 wv = __ldg((const float4*)(Wm + (size_t)row * HH) + lane);
    float4 hv = __ldg((const float4*)(hidden + b * HH) + lane);
    float s = wv.x * hv.x + wv.y * hv.y + wv.z * hv.z + wv.w * hv.w;
    #pragma unroll
    for (int o = 16; o; o >>= 1) s += __shfl_down_sync(FULLMASK, s, o);
    if (lane == 0) {
        float val = s + __ldg(Wb + row);
        g_h[b * HH + row] = val;
        g_u[b * HH + row] = val;
    }
}

// ================================ MEGA KERNEL ================================
__global__ void __launch_bounds__(256, 5)
k_mega(const int* __restrict__ story,
       const float* __restrict__ C,
       const int* __restrict__ lengths,
       const float* __restrict__ W1w, const float* __restrict__ W1b,
       const float* __restrict__ W3w, const float* __restrict__ W3b,
       const float* __restrict__ W4w, const float* __restrict__ W4b,
       float* __restrict__ o_sp, float* __restrict__ o_qh, float* __restrict__ o_qt,
       float* __restrict__ a_sp, float* __restrict__ a_qh, float* __restrict__ a_qt,
       float* __restrict__ o_mask,
       uint32_t k1a, uint32_t k1b, uint32_t k2a, uint32_t k2b,
       uint32_t k3a, uint32_t k3b)
{
    extern __shared__ float s_emb[];     // SPB x E floats = 32KB
    __shared__ float s_logit[SPB];
    __shared__ float red[256];
    __shared__ float sred[8][128];

    const size_t TBL = (size_t)VOCAB * E;
    int bid = blockIdx.x;
    int t = threadIdx.x, lane = t & 31, w = t >> 5;

    // ---------------- head-GEMV blocks ----------------
    if (bid >= GB && bid < GB + HB) {
        int gid = (bid - GB) * 256 + t;
        int hw  = gid >> 5;
        if (hw < HEADW) {
            const float *W, *bias; float* outl; int N, n;
            if (hw < 2)           { W = W1w; bias = W1b; outl = o_sp; N = 2;  n = hw; }
            else if (hw < 2 + NE) { W = W3w; bias = W3b; outl = o_qh; N = NE; n = hw - 2; }
            else                  { W = W4w; bias = W4b; outl = o_qt; N = NR; n = hw - 2 - NE; }
            float4 w4 = __ldg((const float4*)(W + (size_t)n * HH) + lane);
            float  bs = __ldg(bias + n);
            #pragma unroll
            for (int b = 0; b < B; b++) {
                float4 h4 = __ldg((const float4*)(g_h + b * HH) + lane);
                float s = w4.x * h4.x + w4.y * h4.y + w4.z * h4.z + w4.w * h4.w;
                #pragma unroll
                for (int o = 16; o; o >>= 1) s += __shfl_down_sync(FULLMASK, s, o);
                if (lane == 0) outl[b * N + n] = s + bs;
            }
        }
        __threadfence();
        __syncthreads();
        if (t == 0) atomicAdd(&g_headcnt, 1);
        return;
    }

    // ---------------- argmax blocks (spin on head completion) ----------------
    if (bid >= GB + HB) {
        if (t == 0) { while (atomicAdd(&g_headcnt, 0) < HB) { } }
        __syncthreads();
        int blk2 = bid - GB - HB;
        int head = blk2 >> 4, b = blk2 & 15;
        const float* L; float* A; int N; uint32_t ka, kb;
        if (head == 0)      { L = o_sp; A = a_sp; N = 2;  ka = k1a; kb = k1b; }
        else if (head == 1) { L = o_qh; A = a_qh; N = NE; ka = k2a; kb = k2b; }
        else                { L = o_qt; A = a_qt; N = NR; ka = k3a; kb = k3b; }

        float bv = -INFINITY; int bi = 0x7fffffff;
        for (int i = t; i < N; i += 256) {
            int idx = b * N + i;
            float logit = __ldcg(L + idx);   // produced in this kernel -> bypass L1
            uint32_t o0, o1;
            threefry2x32(ka, kb, 0u, (uint32_t)idx, o0, o1);
            uint32_t bits = o0 ^ o1;
            float u = __uint_as_float((bits >> 9) | 0x3F800000u) - 1.0f;
            float v = fmaxf(1e-10f, u + 1e-10f);
            float g = -logf(-logf(v));
            float nv = logit + g;
            if (nv > bv || (nv == bv && i < bi)) { bv = nv; bi = i; }
        }
        float* sv = red;
        int*   si = (int*)&sred[0][0];
        sv[t] = bv; si[t] = bi;
        __syncthreads();
        for (int o = 128; o; o >>= 1) {
            if (t < o) {
                if (sv[t + o] > sv[t] || (sv[t + o] == sv[t] && si[t + o] < si[t])) {
                    sv[t] = sv[t + o]; si[t] = si[t + o];
                }
            }
            __syncthreads();
        }
        int best = si[0];
        float* out = A + b * N;
        for (int i = t; i < N; i += 256) out[i] = (i == best) ? 1.0f : 0.0f;
        return;
    }

    // ======================= gather blocks: full hop chain =======================
    int b     = bid / BPB;
    int blkin = bid % BPB;
    int slot0 = blkin * SPB;
    int sbase = b * S + slot0 + w * SPW;
    int lbase = w * SPW;
    const float* u_b = g_u + b * HH;

    // ---- hop 0: gather C0, logits0 -> s_logit (emb0 single-use) ----
    {
        float4 u4 = __ldg((const float4*)u_b + lane);   // u0 = h, prior kernel
        #pragma unroll 1
        for (int i = 0; i < SPW; i += 2) {
            int s0 = sbase + i, s1 = s0 + 1;
            int4 i0 = __ldg((const int4*)story + s0);
            int4 i1 = __ldg((const int4*)story + s1);
            float4 a0 = __ldg((const float4*)(C + (size_t)i0.x * E) + lane);
            float4 a1 = __ldg((const float4*)(C + (size_t)i0.y * E) + lane);
            float4 a2 = __ldg((const float4*)(C + (size_t)i0.z * E) + lane);
            float4 a3 = __ldg((const float4*)(C + (size_t)i0.w * E) + lane);
            float4 c0 = __ldg((const float4*)(C + (size_t)i1.x * E) + lane);
            float4 c1 = __ldg((const float4*)(C + (size_t)i1.y * E) + lane);
            float4 c2 = __ldg((const float4*)(C + (size_t)i1.z * E) + lane);
            float4 c3 = __ldg((const float4*)(C + (size_t)i1.w * E) + lane);
            float sa = (a0.x + a1.x + a2.x + a3.x) * u4.x
                     + (a0.y + a1.y + a2.y + a3.y) * u4.y
                     + (a0.z + a1.z + a2.z + a3.z) * u4.z
                     + (a0.w + a1.w + a2.w + a3.w) * u4.w;
            float sb = (c0.x + c1.x + c2.x + c3.x) * u4.x
                     + (c0.y + c1.y + c2.y + c3.y) * u4.y
                     + (c0.z + c1.z + c2.z + c3.z) * u4.z
                     + (c0.w + c1.w + c2.w + c3.w) * u4.w;
            #pragma unroll
            for (int o = 16; o; o >>= 1) {
                sa += __shfl_down_sync(FULLMASK, sa, o);
                sb += __shfl_down_sync(FULLMASK, sb, o);
            }
            if (lane == 0) { s_logit[lbase + i] = sa; s_logit[lbase + i + 1] = sb; }
        }
    }
    __syncthreads();
    // block-local softmax partials (warp 0)
    if (w == 0) {
        float v0 = s_logit[lane], v1 = s_logit[lane + 32];
        float mb = fmaxf(v0, v1);
        #pragma unroll
        for (int o = 16; o; o >>= 1) mb = fmaxf(mb, __shfl_xor_sync(FULLMASK, mb, o));
        float sb = expf(v0 - mb) + expf(v1 - mb);
        #pragma unroll
        for (int o = 16; o; o >>= 1) sb += __shfl_xor_sync(FULLMASK, sb, o);
        if (lane == 0) g_stats[0][b * BPB + blkin] = make_float2(mb, sb);
    }
    __threadfence(); __syncthreads();
    if (t == 0) { atomicAdd(&g_cnt[b], 1); while (atomicAdd(&g_cnt[b], 0) < BPB) { } }
    __syncthreads();

    // combine softmax0 stats (32 pairs)
    float m0, inv0;
    {
        if (w == 0) {
            float2 st;
            st.x = __ldcg(&g_stats[0][b * BPB + lane].x);
            st.y = __ldcg(&g_stats[0][b * BPB + lane].y);
            float mm = st.x;
            #pragma unroll
            for (int o = 16; o; o >>= 1) mm = fmaxf(mm, __shfl_xor_sync(FULLMASK, mm, o));
            float ss = st.y * expf(st.x - mm);
            #pragma unroll
            for (int o = 16; o; o >>= 1) ss += __shfl_xor_sync(FULLMASK, ss, o);
            if (lane == 0) { red[0] = mm; red[1] = 1.0f / ss; }
        }
        __syncthreads();
        m0 = red[0]; inv0 = red[1];
        __syncthreads();
    }

    // ---- hop 1: gather C1 -> smem emb, u += sum p0 * emb ----
    {
        const float* Ct = C + TBL;
        float4 acc = make_float4(0.f, 0.f, 0.f, 0.f);
        #pragma unroll 1
        for (int i = 0; i < SPW; i += 2) {
            int s0 = sbase + i, s1 = s0 + 1;
            int4 i0 = __ldg((const int4*)story + s0);
            int4 i1 = __ldg((const int4*)story + s1);
            float p0 = expf(s_logit[lbase + i] - m0) * inv0;
            float p1 = expf(s_logit[lbase + i + 1] - m0) * inv0;
            float4 a0 = __ldg((const float4*)(Ct + (size_t)i0.x * E) + lane);
            float4 a1 = __ldg((const float4*)(Ct + (size_t)i0.y * E) + lane);
            float4 a2 = __ldg((const float4*)(Ct + (size_t)i0.z * E) + lane);
            float4 a3 = __ldg((const float4*)(Ct + (size_t)i0.w * E) + lane);
            float4 c0 = __ldg((const float4*)(Ct + (size_t)i1.x * E) + lane);
            float4 c1 = __ldg((const float4*)(Ct + (size_t)i1.y * E) + lane);
            float4 c2 = __ldg((const float4*)(Ct + (size_t)i1.z * E) + lane);
            float4 c3 = __ldg((const float4*)(Ct + (size_t)i1.w * E) + lane);
            float4 v0 = make_float4(a0.x + a1.x + a2.x + a3.x, a0.y + a1.y + a2.y + a3.y,
                                    a0.z + a1.z + a2.z + a3.z, a0.w + a1.w + a2.w + a3.w);
            float4 v1 = make_float4(c0.x + c1.x + c2.x + c3.x, c0.y + c1.y + c2.y + c3.y,
                                    c0.z + c1.z + c2.z + c3.z, c0.w + c1.w + c2.w + c3.w);
            *((float4*)&s_emb[(lbase + i) * E] + lane)     = v0;
            *((float4*)&s_emb[(lbase + i + 1) * E] + lane) = v1;
            acc.x = fmaf(p0, v0.x, acc.x); acc.y = fmaf(p0, v0.y, acc.y);
            acc.z = fmaf(p0, v0.z, acc.z); acc.w = fmaf(p0, v0.w, acc.w);
            acc.x = fmaf(p1, v1.x, acc.x); acc.y = fmaf(p1, v1.y, acc.y);
            acc.z = fmaf(p1, v1.z, acc.z); acc.w = fmaf(p1, v1.w, acc.w);
        }
        *((float4*)&sred[w][lane * 4]) = acc;
        __syncthreads();
        if (t < 128) {
            float v = sred[0][t];
            #pragma unroll
            for (int ww = 1; ww < 8; ww++) v += sred[ww][t];
            atomicAdd(&g_u[b * HH + t], v);
        }
    }
    __threadfence(); __syncthreads();
    if (t == 0) { atomicAdd(&g_cnt[B + b], 1); while (atomicAdd(&g_cnt[B + b], 0) < BPB) { } }
    __syncthreads();

    // ---- logits1 = emb1 . u1 -> s_logit, then block partials ----
    {
        float4 u4;
        u4.x = __ldcg(g_u + b * HH + lane * 4 + 0);
        u4.y = __ldcg(g_u + b * HH + lane * 4 + 1);
        u4.z = __ldcg(g_u + b * HH + lane * 4 + 2);
        u4.w = __ldcg(g_u + b * HH + lane * 4 + 3);
        #pragma unroll 1
        for (int i = 0; i < SPW; i++) {
            float4 e = *((const float4*)&s_emb[(lbase + i) * E] + lane);
            float d = e.x * u4.x + e.y * u4.y + e.z * u4.z + e.w * u4.w;
            #pragma unroll
            for (int o = 16; o; o >>= 1) d += __shfl_down_sync(FULLMASK, d, o);
            if (lane == 0) s_logit[lbase + i] = d;
        }
    }
    __syncthreads();
    if (w == 0) {
        float v0 = s_logit[lane], v1 = s_logit[lane + 32];
        float mb = fmaxf(v0, v1);
        #pragma unroll
        for (int o = 16; o; o >>= 1) mb = fmaxf(mb, __shfl_xor_sync(FULLMASK, mb, o));
        float sb = expf(v0 - mb) + expf(v1 - mb);
        #pragma unroll
        for (int o = 16; o; o >>= 1) sb += __shfl_xor_sync(FULLMASK, sb, o);
        if (lane == 0) g_stats[1][b * BPB + blkin] = make_float2(mb, sb);
    }
    __threadfence(); __syncthreads();
    if (t == 0) { atomicAdd(&g_cnt[2 * B + b], 1); while (atomicAdd(&g_cnt[2 * B + b], 0) < BPB) { } }
    __syncthreads();

    // combine softmax1 stats
    float m1, inv1;
    {
        if (w == 0) {
            float2 st;
            st.x = __ldcg(&g_stats[1][b * BPB + lane].x);
            st.y = __ldcg(&g_stats[1][b * BPB + lane].y);
            float mm = st.x;
            #pragma unroll
            for (int o = 16; o; o >>= 1) mm = fmaxf(mm, __shfl_xor_sync(FULLMASK, mm, o));
            float ss = st.y * expf(st.x - mm);
            #pragma unroll
            for (int o = 16; o; o >>= 1) ss += __shfl_xor_sync(FULLMASK, ss, o);
            if (lane == 0) { red[0] = mm; red[1] = 1.0f / ss; }
        }
        __syncthreads();
        m1 = red[0]; inv1 = red[1];
        __syncthreads();
    }

    // ---- hop 2: gather C2 -> smem emb (overwrite), u += sum p1 * emb ----
    {
        const float* Ct = C + 2 * TBL;
        float4 acc = make_float4(0.f, 0.f, 0.f, 0.f);
        #pragma unroll 1
        for (int i = 0; i < SPW; i += 2) {
            int s0 = sbase + i, s1 = s0 + 1;
            int4 i0 = __ldg((const int4*)story + s0);
            int4 i1 = __ldg((const int4*)story + s1);
            float p0 = expf(s_logit[lbase + i] - m1) * inv1;
            float p1 = expf(s_logit[lbase + i + 1] - m1) * inv1;
            float4 a0 = __ldg((const float4*)(Ct + (size_t)i0.x * E) + lane);
            float4 a1 = __ldg((const float4*)(Ct + (size_t)i0.y * E) + lane);
            float4 a2 = __ldg((const float4*)(Ct + (size_t)i0.z * E) + lane);
            float4 a3 = __ldg((const float4*)(Ct + (size_t)i0.w * E) + lane);
            float4 c0 = __ldg((const float4*)(Ct + (size_t)i1.x * E) + lane);
            float4 c1 = __ldg((const float4*)(Ct + (size_t)i1.y * E) + lane);
            float4 c2 = __ldg((const float4*)(Ct + (size_t)i1.z * E) + lane);
            float4 c3 = __ldg((const float4*)(Ct + (size_t)i1.w * E) + lane);
            float4 v0 = make_float4(a0.x + a1.x + a2.x + a3.x, a0.y + a1.y + a2.y + a3.y,
                                    a0.z + a1.z + a2.z + a3.z, a0.w + a1.w + a2.w + a3.w);
            float4 v1 = make_float4(c0.x + c1.x + c2.x + c3.x, c0.y + c1.y + c2.y + c3.y,
                                    c0.z + c1.z + c2.z + c3.z, c0.w + c1.w + c2.w + c3.w);
            *((float4*)&s_emb[(lbase + i) * E] + lane)     = v0;
            *((float4*)&s_emb[(lbase + i + 1) * E] + lane) = v1;
            acc.x = fmaf(p0, v0.x, acc.x); acc.y = fmaf(p0, v0.y, acc.y);
            acc.z = fmaf(p0, v0.z, acc.z); acc.w = fmaf(p0, v0.w, acc.w);
            acc.x = fmaf(p1, v1.x, acc.x); acc.y = fmaf(p1, v1.y, acc.y);
            acc.z = fmaf(p1, v1.z, acc.z); acc.w = fmaf(p1, v1.w, acc.w);
        }
        *((float4*)&sred[w][lane * 4]) = acc;
        __syncthreads();
        if (t < 128) {
            float v = sred[0][t];
            #pragma unroll
            for (int ww = 1; ww < 8; ww++) v += sred[ww][t];
            atomicAdd(&g_u[b * HH + t], v);
        }
    }
    __threadfence(); __syncthreads();
    if (t == 0) { atomicAdd(&g_cnt[3 * B + b], 1); while (atomicAdd(&g_cnt[3 * B + b], 0) < BPB) { } }
    __syncthreads();

    // ---- final: logits2 = emb2 . u2 -> sigmoid + length mask -> out ----
    {
        float4 u4;
        u4.x = __ldcg(g_u + b * HH + lane * 4 + 0);
        u4.y = __ldcg(g_u + b * HH + lane * 4 + 1);
        u4.z = __ldcg(g_u + b * HH + lane * 4 + 2);
        u4.w = __ldcg(g_u + b * HH + lane * 4 + 3);
        int len = __ldg(lengths + b);
        #pragma unroll 1
        for (int i = 0; i < SPW; i++) {
            float4 e = *((const float4*)&s_emb[(lbase + i) * E] + lane);
            float d = e.x * u4.x + e.y * u4.y + e.z * u4.z + e.w * u4.w;
            #pragma unroll
            for (int o = 16; o; o >>= 1) d += __shfl_down_sync(FULLMASK, d, o);
            if (lane == 0) {
                int sl = slot0 + w * SPW + i;
                o_mask[b * S + sl] = (sl < len) ? 1.0f / (1.0f + expf(-d)) : 0.0f;
            }
        }
    }
}

// ---------------- host launch ----------------
extern "C" void kernel_launch(void* const* d_in, const int* in_sizes, int n_in,
                              void* d_out, int out_size)
{
    const int*   story   = (const int*)d_in[0];
    const int*   lengths = (const int*)d_in[1];
    const float* hidden  = (const float*)d_in[2];
    // d_in[3] global_pointer: unused (is_decoding == 0 path)
    const float* C       = (const float*)d_in[4];
    const float* Wm      = (const float*)d_in[5];
    const float* Wb      = (const float*)d_in[6];
    const float* W1w     = (const float*)d_in[7];
    const float* W1b     = (const float*)d_in[8];
    const float* W3w     = (const float*)d_in[9];
    const float* W3b     = (const float*)d_in[10];
    const float* W4w     = (const float*)d_in[11];
    const float* W4b     = (const float*)d_in[12];

    float* out = (float*)d_out;
    float* o_sp   = out;                       // [B,2]
    float* o_spa  = out + B * 2;               // [B,2]
    float* o_qh   = out + B * 4;               // [B,4000]
    float* o_qha  = o_qh + B * NE;             // [B,4000]
    float* o_qt   = o_qha + B * NE;            // [B,200]
    float* o_qta  = o_qt + B * NR;             // [B,200]
    float* o_mask = o_qta + B * NR;            // [B,S]

    // JAX partitionable split of key(42): k_i = threefry(key, (0, i))
    uint32_t k1a, k1b, k2a, k2b, k3a, k3b;
    threefry2x32(0u, 42u, 0u, 0u, k1a, k1b);
    threefry2x32(0u, 42u, 0u, 1u, k2a, k2b);
    threefry2x32(0u, 42u, 0u, 2u, k3a, k3b);

    const int SMEM = SPB * E * sizeof(float);  // 32KB dynamic

    // 1) h = hidden@Wm^T + b ; u = h ; reset counters (warp per output)
    k_h<<<256, 256>>>(hidden, Wm, Wb);

    // 2) everything else: hop chain (512 barrier blocks) + heads + argmax
    k_mega<<<GB + HB + AB, 256, SMEM>>>(
        story, C, lengths,
        W1w, W1b, W3w, W3b, W4w, W4b,
        o_sp, o_qh, o_qt, o_spa, o_qha, o_qta, o_mask,
        k1a, k1b, k2a, k2b, k3a, k3b);
}